// round 1
// baseline (speedup 1.0000x reference)
#include <cuda_runtime.h>
#include <math_constants.h>
#include <cstdint>

#define BATCH 8
#define NPTS  4096
#define KNN   20
#define CIN   26      // 2*D + K
#define C1    64
#define C2    64
#define C3    128
#define C4    256
#define CCAT  512
#define EMB   512

// Scratch (device globals: sanctioned, no runtime allocation)
__device__ int   g_idx[BATCH * NPTS * KNN];                 // 2.6 MB
__device__ float g_cat[(size_t)BATCH * NPTS * CCAT];        // 64 MB

// ---------------------------------------------------------------------------
// Kernel 1: exact 20-NN per point.
// Rank key v = sq_m - 2*x_n.x_m  (ascending v == descending reference "pair").
// Ties broken by lower index (strict-less insertion while scanning m ascending)
// which matches jax.lax.top_k tie-breaking.
// ---------------------------------------------------------------------------
__global__ __launch_bounds__(128) void knn_kernel(const float* __restrict__ x) {
    extern __shared__ float4 xs[];   // 4096 * 16B = 64KB
    const int b = blockIdx.y;
    const float* xb = x + (size_t)b * 3 * NPTS;

    for (int m = threadIdx.x; m < NPTS; m += blockDim.x) {
        float x0 = xb[m], x1 = xb[NPTS + m], x2 = xb[2 * NPTS + m];
        float sq = fmaf(x0, x0, fmaf(x1, x1, x2 * x2));
        xs[m] = make_float4(x0, x1, x2, sq);
    }
    __syncthreads();

    const int n = blockIdx.x * blockDim.x + threadIdx.x;
    float4 p = xs[n];
    const float a0 = -2.0f * p.x, a1 = -2.0f * p.y, a2 = -2.0f * p.z;

    float bv[KNN];
    int   bi[KNN];
#pragma unroll
    for (int t = 0; t < KNN; ++t) { bv[t] = CUDART_INF_F; bi[t] = -1; }

#pragma unroll 4
    for (int m = 0; m < NPTS; ++m) {
        float4 q = xs[m];
        float v = fmaf(a0, q.x, fmaf(a1, q.y, fmaf(a2, q.z, q.w)));
        if (v < bv[KNN - 1]) {
            bool ins = true;
#pragma unroll
            for (int t = KNN - 1; t >= 1; --t) {
                bool shift = v < bv[t - 1];
                if (shift)      { bv[t] = bv[t - 1]; bi[t] = bi[t - 1]; }
                else if (ins)   { bv[t] = v;         bi[t] = m; }
                ins = shift;
            }
            if (ins) { bv[0] = v; bi[0] = m; }
        }
    }

    int* outp = g_idx + ((size_t)b * NPTS + n) * KNN;
#pragma unroll
    for (int t = 0; t < KNN; ++t) outp[t] = bi[t];
}

// ---------------------------------------------------------------------------
// Kernel 2: fused graph-feature + 4 conv layers + per-k max -> cat (32768x512)
// All weights transposed into smem ([c][o] layout), 1 block/SM, 512 threads.
// ---------------------------------------------------------------------------
#define PTS_PER_BLK 16

__global__ __launch_bounds__(512, 1) void mlp_kernel(
    const float* __restrict__ x,
    const float* __restrict__ w1, const float* __restrict__ w2,
    const float* __restrict__ w3, const float* __restrict__ w4) {

    extern __shared__ float sm[];
    float* W1t   = sm;                    // 26*64   = 1664
    float* W2t   = W1t + CIN * C1;        // 64*64   = 4096
    float* W3t   = W2t + C2 * C2;         // 64*128  = 8192
    float* W4t   = W3t + C2 * C3;         // 128*256 = 32768
    float* h1    = W4t + C3 * C4;         // 20*64
    float* h2    = h1 + KNN * C1;         // 20*64   (reused as partial-max)
    float* h3    = h2 + KNN * C2;         // 20*128
    float* s_nbr = h3 + KNN * C3;         // 20*4
    float* s_dist= s_nbr + KNN * 4;       // 20
    float* s_base= s_dist + KNN;          // 64
    float* s_cat = s_base + C1;           // 512
    float* s_xn  = s_cat + CCAT;          // 4

    const int tid = threadIdx.x;

    // -- stage transposed weights into smem (coalesced gmem reads) --
    for (int i = tid; i < C1 * CIN; i += 512) { int o = i / CIN, c = i % CIN; W1t[c * C1 + o] = w1[i]; }
    for (int i = tid; i < C2 * C2;  i += 512) { int o = i >> 6,  c = i & 63;  W2t[c * C2 + o] = w2[i]; }
    for (int i = tid; i < C3 * C2;  i += 512) { int o = i >> 6,  c = i & 63;  W3t[c * C3 + o] = w3[i]; }
    for (int i = tid; i < C4 * C3;  i += 512) { int o = i >> 7,  c = i & 127; W4t[c * C4 + o] = w4[i]; }
    __syncthreads();

    for (int pp = 0; pp < PTS_PER_BLK; ++pp) {
        const int pt = blockIdx.x * PTS_PER_BLK + pp;
        const int b  = pt >> 12;
        const int n  = pt & (NPTS - 1);
        const float* xb = x + (size_t)b * 3 * NPTS;

        // ---- stage A: gather neighbors, dist ----
        if (tid < 3) s_xn[tid] = xb[tid * NPTS + n];
        if (tid < KNN) {
            int nb = g_idx[((size_t)b * NPTS + n) * KNN + tid];
            float c0 = xb[n], c1 = xb[NPTS + n], c2 = xb[2 * NPTS + n];
            float n0 = xb[nb], n1 = xb[NPTS + nb], n2 = xb[2 * NPTS + nb];
            s_nbr[tid * 4 + 0] = n0;
            s_nbr[tid * 4 + 1] = n1;
            s_nbr[tid * 4 + 2] = n2;
            float d0 = n0 - c0, d1 = n1 - c1, d2 = n2 - c2;
            s_dist[tid] = sqrtf(fmaf(d0, d0, fmaf(d1, d1, d2 * d2)) + 1e-12f);
        }
        __syncthreads();

        // ---- stage B: layer-1 constant part (xc + distr columns) ----
        if (tid < C1) {
            float acc = 0.0f;
#pragma unroll
            for (int d = 0; d < 3; ++d) acc = fmaf(W1t[d * C1 + tid], s_xn[d], acc);
#pragma unroll
            for (int j = 0; j < KNN; ++j) acc = fmaf(W1t[(6 + j) * C1 + tid], s_dist[j], acc);
            s_base[tid] = acc;
        }
        __syncthreads();

        // ---- layer 1: h1[k][o] = relu(base[o] + W1[:,3:6].nbr_k) ----
        {
            int o = tid & 63, g = tid >> 6;          // g in 0..7
            float wa = W1t[3 * C1 + o], wb = W1t[4 * C1 + o], wc = W1t[5 * C1 + o];
            float base = s_base[o];
#pragma unroll
            for (int j = 0; j < 3; ++j) {
                int k = g + 8 * j;
                if (j < 2 || g < 4) {
                    float v = fmaf(wa, s_nbr[k * 4 + 0],
                              fmaf(wb, s_nbr[k * 4 + 1],
                              fmaf(wc, s_nbr[k * 4 + 2], base)));
                    h1[k * C1 + o] = fmaxf(v, 0.0f);
                }
            }
        }
        __syncthreads();

        // ---- layer 2: 64 -> 64 ----
        {
            int o = tid & 63, g = tid >> 6;          // k = g, g+8, g+16(g<4)
            float a0 = 0.f, a1 = 0.f, a2 = 0.f;
#pragma unroll
            for (int c = 0; c < C2; c += 4) {
                float w0 = W2t[(c + 0) * C2 + o];
                float wA = W2t[(c + 1) * C2 + o];
                float wB = W2t[(c + 2) * C2 + o];
                float wC = W2t[(c + 3) * C2 + o];
                float4 hA = *(const float4*)(h1 + (g)      * C1 + c);
                float4 hB = *(const float4*)(h1 + (g + 8)  * C1 + c);
                a0 = fmaf(w0, hA.x, fmaf(wA, hA.y, fmaf(wB, hA.z, fmaf(wC, hA.w, a0))));
                a1 = fmaf(w0, hB.x, fmaf(wA, hB.y, fmaf(wB, hB.z, fmaf(wC, hB.w, a1))));
                if (g < 4) {
                    float4 hC = *(const float4*)(h1 + (g + 16) * C1 + c);
                    a2 = fmaf(w0, hC.x, fmaf(wA, hC.y, fmaf(wB, hC.z, fmaf(wC, hC.w, a2))));
                }
            }
            h2[(g)      * C2 + o] = fmaxf(a0, 0.f);
            h2[(g + 8)  * C2 + o] = fmaxf(a1, 0.f);
            if (g < 4) h2[(g + 16) * C2 + o] = fmaxf(a2, 0.f);
        }
        __syncthreads();

        // ---- layer 3: 64 -> 128 ----
        {
            int o = tid & 127, g = tid >> 7;         // g in 0..3, k = g + 4j
            float acc[5] = {0.f, 0.f, 0.f, 0.f, 0.f};
#pragma unroll
            for (int c = 0; c < C2; c += 4) {
                float w0 = W3t[(c + 0) * C3 + o];
                float wA = W3t[(c + 1) * C3 + o];
                float wB = W3t[(c + 2) * C3 + o];
                float wC = W3t[(c + 3) * C3 + o];
#pragma unroll
                for (int j = 0; j < 5; ++j) {
                    float4 h = *(const float4*)(h2 + (g + 4 * j) * C2 + c);
                    acc[j] = fmaf(w0, h.x, fmaf(wA, h.y, fmaf(wB, h.z, fmaf(wC, h.w, acc[j]))));
                }
            }
#pragma unroll
            for (int j = 0; j < 5; ++j)
                h3[(g + 4 * j) * C3 + o] = fmaxf(acc[j], 0.f);
        }
        __syncthreads();

        // ---- layer 4: 128 -> 256 (accumulate in regs, fuse max) ----
        float acc4[10];
        {
#pragma unroll
            for (int j = 0; j < 10; ++j) acc4[j] = 0.f;
            int o = tid & 255, g = tid >> 8;         // g in 0..1, k = g + 2j
#pragma unroll 8
            for (int c = 0; c < C3; c += 4) {
                float w0 = W4t[(c + 0) * C4 + o];
                float wA = W4t[(c + 1) * C4 + o];
                float wB = W4t[(c + 2) * C4 + o];
                float wC = W4t[(c + 3) * C4 + o];
#pragma unroll
                for (int j = 0; j < 10; ++j) {
                    float4 h = *(const float4*)(h3 + (g + 2 * j) * C3 + c);
                    acc4[j] = fmaf(w0, h.x, fmaf(wA, h.y, fmaf(wB, h.z, fmaf(wC, h.w, acc4[j]))));
                }
            }
        }

        // ---- maxes x1..x3 (reads of h1..h3 only) ----
        if (tid < 64) {
            float m = 0.f;
#pragma unroll
            for (int k = 0; k < KNN; ++k) m = fmaxf(m, h1[k * C1 + tid]);
            s_cat[tid] = m;
        } else if (tid < 128) {
            int o = tid - 64; float m = 0.f;
#pragma unroll
            for (int k = 0; k < KNN; ++k) m = fmaxf(m, h2[k * C2 + o]);
            s_cat[64 + o] = m;
        } else if (tid < 256) {
            int o = tid - 128; float m = 0.f;
#pragma unroll
            for (int k = 0; k < KNN; ++k) m = fmaxf(m, h3[k * C3 + o]);
            s_cat[128 + o] = m;
        }
        __syncthreads();   // h2 reads done -> safe to reuse as partial-max

        {
            int o = tid & 255, g = tid >> 8;
            float pm = 0.f;   // relu folded: max(relu(a)) = max(0, max a)
#pragma unroll
            for (int j = 0; j < 10; ++j) pm = fmaxf(pm, acc4[j]);
            h2[g * 256 + o] = pm;
        }
        __syncthreads();
        if (tid < 256) s_cat[256 + tid] = fmaxf(h2[tid], h2[256 + tid]);
        __syncthreads();

        g_cat[(size_t)pt * CCAT + tid] = s_cat[tid];
        __syncthreads();   // protect smem before next point
    }
}

// ---------------------------------------------------------------------------
// Kernel 3: out[b][o][n] = relu(sum_c w5[o][c] * cat[b][n][c])
// 64x64 tile, 256 threads, 4x4 micro-tile.
// ---------------------------------------------------------------------------
__global__ __launch_bounds__(256) void gemm5_kernel(const float* __restrict__ w5,
                                                    float* __restrict__ out) {
    __shared__ __align__(16) float As[16][68];   // w5 chunk  [c][o]
    __shared__ __align__(16) float Bs[16][68];   // cat chunk [c][n]

    const int b  = blockIdx.z;
    const int o0 = blockIdx.y * 64;
    const int n0 = blockIdx.x * 64;
    const float* cat = g_cat + (size_t)b * NPTS * CCAT;

    const int tx = threadIdx.x & 15;
    const int ty = threadIdx.x >> 4;

    float acc[4][4];
#pragma unroll
    for (int i = 0; i < 4; ++i)
#pragma unroll
        for (int j = 0; j < 4; ++j) acc[i][j] = 0.f;

    const int lrow = threadIdx.x >> 2;          // 0..63
    const int lcc  = (threadIdx.x & 3) * 4;     // 0,4,8,12

    for (int c0 = 0; c0 < CCAT; c0 += 16) {
        float4 av = *(const float4*)(w5 + (size_t)(o0 + lrow) * CCAT + c0 + lcc);
        float4 bv = *(const float4*)(cat + (size_t)(n0 + lrow) * CCAT + c0 + lcc);
        As[lcc + 0][lrow] = av.x; As[lcc + 1][lrow] = av.y;
        As[lcc + 2][lrow] = av.z; As[lcc + 3][lrow] = av.w;
        Bs[lcc + 0][lrow] = bv.x; Bs[lcc + 1][lrow] = bv.y;
        Bs[lcc + 2][lrow] = bv.z; Bs[lcc + 3][lrow] = bv.w;
        __syncthreads();

#pragma unroll
        for (int c = 0; c < 16; ++c) {
            float4 a = *(const float4*)(&As[c][ty * 4]);
            float4 bb = *(const float4*)(&Bs[c][tx * 4]);
            acc[0][0] = fmaf(a.x, bb.x, acc[0][0]); acc[0][1] = fmaf(a.x, bb.y, acc[0][1]);
            acc[0][2] = fmaf(a.x, bb.z, acc[0][2]); acc[0][3] = fmaf(a.x, bb.w, acc[0][3]);
            acc[1][0] = fmaf(a.y, bb.x, acc[1][0]); acc[1][1] = fmaf(a.y, bb.y, acc[1][1]);
            acc[1][2] = fmaf(a.y, bb.z, acc[1][2]); acc[1][3] = fmaf(a.y, bb.w, acc[1][3]);
            acc[2][0] = fmaf(a.z, bb.x, acc[2][0]); acc[2][1] = fmaf(a.z, bb.y, acc[2][1]);
            acc[2][2] = fmaf(a.z, bb.z, acc[2][2]); acc[2][3] = fmaf(a.z, bb.w, acc[2][3]);
            acc[3][0] = fmaf(a.w, bb.x, acc[3][0]); acc[3][1] = fmaf(a.w, bb.y, acc[3][1]);
            acc[3][2] = fmaf(a.w, bb.z, acc[3][2]); acc[3][3] = fmaf(a.w, bb.w, acc[3][3]);
        }
        __syncthreads();
    }

#pragma unroll
    for (int i = 0; i < 4; ++i) {
        int o = o0 + ty * 4 + i;
        float4 r;
        r.x = fmaxf(acc[i][0], 0.f); r.y = fmaxf(acc[i][1], 0.f);
        r.z = fmaxf(acc[i][2], 0.f); r.w = fmaxf(acc[i][3], 0.f);
        *(float4*)(out + ((size_t)b * EMB + o) * NPTS + n0 + tx * 4) = r;
    }
}

// ---------------------------------------------------------------------------
extern "C" void kernel_launch(void* const* d_in, const int* in_sizes, int n_in,
                              void* d_out, int out_size) {
    const float* x  = (const float*)d_in[0];
    const float* w1 = (const float*)d_in[1];
    const float* w2 = (const float*)d_in[2];
    const float* w3 = (const float*)d_in[3];
    const float* w4 = (const float*)d_in[4];
    const float* w5 = (const float*)d_in[5];
    float* out = (float*)d_out;

    const int knn_smem = NPTS * sizeof(float4);                 // 64 KB
    const int mlp_smem = (CIN * C1 + C2 * C2 + C2 * C3 + C3 * C4 +
                          KNN * C1 + KNN * C2 + KNN * C3 +
                          KNN * 4 + KNN + C1 + CCAT + 4) * sizeof(float);  // ~210 KB

    cudaFuncSetAttribute(knn_kernel, cudaFuncAttributeMaxDynamicSharedMemorySize, knn_smem);
    cudaFuncSetAttribute(mlp_kernel, cudaFuncAttributeMaxDynamicSharedMemorySize, mlp_smem);

    knn_kernel<<<dim3(NPTS / 128, BATCH), 128, knn_smem>>>(x);
    mlp_kernel<<<(BATCH * NPTS) / PTS_PER_BLK, 512, mlp_smem>>>(x, w1, w2, w3, w4);
    gemm5_kernel<<<dim3(NPTS / 64, EMB / 64, BATCH), 256>>>(w5, out);
}